// round 3
// baseline (speedup 1.0000x reference)
#include <cuda_runtime.h>
#include <cuda_bf16.h>
#include <cstdint>

// ---------------------------------------------------------------------------
// Problem constants
// ---------------------------------------------------------------------------
#define OC      8192
#define IC      8192
#define BATCH   64
#define PROWS   4096      // packed rows (OC/2)
#define KSPLIT  4

// ---- tcgen05 path config ----
#define TC_TILE_M  128            // packed rows per CTA
#define TC_KS_LEN  (IC / KSPLIT)  // 2048
#define TC_KCHUNK  128
#define TC_NCHUNKS (TC_KS_LEN / TC_KCHUNK) // 16
#define NTHREADS   256

// idesc: kind::f16, bf16 x bf16, fp32 accum, M=128, N=128
#define MMA_IDESC (0x490u | (16u << 17) | (8u << 24))

#define SMEM_TMEM_PTR 0
#define SMEM_MBAR     16
#define SMEM_BUF0     1024
#define BUF_STRIDE    98304       // A_low 32K + A_high 32K + B 32K
#define A_HIGH_OFF    32768
#define B_OFF         65536
#define TC_SMEM_TOTAL (1024 + 2 * BUF_STRIDE)   // 197632

// ---- mma.sync fallback config ----
#define FB_TILE_P   64                 // packed rows per CTA -> 128 oc
#define FB_KEXT     (IC / KSPLIT)      // 2048
#define FB_KC       64
#define FB_NCH      (FB_KEXT / FB_KC)  // 32
#define SA_STRIDE   72                 // ints per row (padded)
#define SB_STRIDE   72                 // bf16 per row (padded)
#define FB_SA_BYTES (2 * FB_TILE_P * SA_STRIDE * 4)   // 36864
#define FB_SB_BYTES (2 * 128 * SB_STRIDE * 2)         // 36864
#define FB_SMEM_TOTAL (FB_SA_BYTES + FB_SB_BYTES)     // 73728

// ---------------------------------------------------------------------------
// Scratch (device globals; allocation-free contract)
// ---------------------------------------------------------------------------
__device__ __nv_bfloat16 g_xhl[2 * BATCH * IC];          // [128, 8192] hi rows then lo rows
__device__ float         g_S[BATCH];
__device__ float         g_partial[8 * BATCH * OC];      // [8 slots][64][8192]

// ---------------------------------------------------------------------------
// Generic helpers (valid on plain sm_103)
// ---------------------------------------------------------------------------
__device__ __forceinline__ uint32_t smem_u32(const void* p) {
    uint32_t a;
    asm("{ .reg .u64 t; cvta.to.shared.u64 t, %1; cvt.u32.u64 %0, t; }" : "=r"(a) : "l"(p));
    return a;
}

__device__ __forceinline__ void cp16(uint32_t dst, const void* src) {
    asm volatile("cp.async.cg.shared.global [%0], [%1], 16;" :: "r"(dst), "l"(src));
}
#define CP_COMMIT() asm volatile("cp.async.commit_group;" ::: "memory")
#define CP_WAIT1()  asm volatile("cp.async.wait_group 1;" ::: "memory")

__device__ __forceinline__ void mma16816(float* c, const uint32_t* a, const uint32_t* b) {
    asm volatile("mma.sync.aligned.m16n8k16.row.col.f32.bf16.bf16.f32 "
                 "{%0,%1,%2,%3}, {%4,%5,%6,%7}, {%8,%9}, {%0,%1,%2,%3};"
                 : "+f"(c[0]), "+f"(c[1]), "+f"(c[2]), "+f"(c[3])
                 : "r"(a[0]), "r"(a[1]), "r"(a[2]), "r"(a[3]), "r"(b[0]), "r"(b[1]));
}

// ---------------------------------------------------------------------------
// Kernel 1: split x into bf16 hi/lo components, compute per-row sums S
// ---------------------------------------------------------------------------
__global__ void prep_kernel(const float* __restrict__ x) {
    __shared__ float red[256];
    const int b = blockIdx.x;
    float s = 0.f;
    for (int c = threadIdx.x; c < IC; c += 256) {
        float v = x[b * IC + c];
        __nv_bfloat16 h = __float2bfloat16(v);
        float hf = __bfloat162float(h);
        __nv_bfloat16 l = __float2bfloat16(v - hf);
        g_xhl[b * IC + c] = h;
        g_xhl[(BATCH + b) * IC + c] = l;
        s += v;
    }
    red[threadIdx.x] = s;
    __syncthreads();
    for (int off = 128; off > 0; off >>= 1) {
        if (threadIdx.x < off) red[threadIdx.x] += red[threadIdx.x + off];
        __syncthreads();
    }
    if (threadIdx.x == 0) g_S[b] = red[0];
}

// ---------------------------------------------------------------------------
// tcgen05-specific helpers + kernel (compiled only when sm_103a features exist)
// ---------------------------------------------------------------------------
#if defined(__CUDA_ARCH__) && defined(__CUDA_ARCH_FEAT_SM103_ALL)
#define HAVE_TCGEN05 1
#endif

#ifdef HAVE_TCGEN05
__device__ __forceinline__ uint32_t elect_one() {
    uint32_t pred;
    asm volatile("{\n\t.reg .pred p;\n\telect.sync _|p, 0xFFFFFFFF;\n\tselp.b32 %0, 1, 0, p;\n\t}"
                 : "=r"(pred));
    return pred;
}

#define TCGEN05_ALLOC(smem_addr, nCols) \
    asm volatile("tcgen05.alloc.cta_group::1.sync.aligned.shared::cta.b32 [%0], %1;" \
                 :: "r"((uint32_t)(smem_addr)), "r"((uint32_t)(nCols)) : "memory")
#define TCGEN05_DEALLOC(tmem_addr, nCols) \
    asm volatile("tcgen05.dealloc.cta_group::1.sync.aligned.b32 %0, %1;" \
                 :: "r"(tmem_addr), "r"((uint32_t)(nCols)))
#define TCGEN05_RELINQUISH() \
    asm volatile("tcgen05.relinquish_alloc_permit.cta_group::1.sync.aligned;")
#define TCGEN05_COMMIT(mbar) \
    asm volatile("tcgen05.commit.cta_group::1.mbarrier::arrive::one.shared::cluster.b64 [%0];" \
                 :: "r"((uint32_t)(mbar)) : "memory")
#define TCGEN05_FENCE_BEFORE() asm volatile("tcgen05.fence::before_thread_sync;" ::: "memory")
#define TCGEN05_FENCE_AFTER()  asm volatile("tcgen05.fence::after_thread_sync;" ::: "memory")
#define TCGEN05_WAIT_LD()      asm volatile("tcgen05.wait::ld.sync.aligned;" ::: "memory")

#define MBARRIER_INIT(mbar, cnt) \
    asm volatile("mbarrier.init.shared.b64 [%0], %1;" \
                 :: "r"((uint32_t)(mbar)), "r"((uint32_t)(cnt)) : "memory")

#define MBARRIER_WAIT_PARITY(mbar_addr, phase_parity) do {                              \
    uint32_t _mbar = (uint32_t)(mbar_addr);                                             \
    uint32_t _par  = (uint32_t)(phase_parity);                                          \
    uint32_t _done;                                                                     \
    asm volatile("{\n\t.reg .pred p;\n\t"                                               \
                 "mbarrier.try_wait.parity.acquire.cta.shared::cta.b64 p, [%1], %2;\n\t"\
                 "selp.b32 %0, 1, 0, p;\n\t}"                                           \
                 : "=r"(_done) : "r"(_mbar), "r"(_par) : "memory");                     \
    if (!_done) {                                                                       \
        asm volatile("{\n\t.reg .pred P1;\n\t"                                          \
            "WAIT_LOOP_%=:\n\t"                                                         \
            "mbarrier.try_wait.parity.acquire.cta.shared::cta.b64 P1, [%0], %1, 0x989680;\n\t" \
            "@P1 bra.uni WAIT_DONE_%=;\n\t"                                             \
            "bra.uni WAIT_LOOP_%=;\n\t"                                                 \
            "WAIT_DONE_%=:\n\t}"                                                        \
            :: "r"(_mbar), "r"(_par) : "memory");                                       \
    }                                                                                   \
} while (0)

#define TCGEN05_LD_X32(r, tmem_addr)                                                    \
    asm volatile("tcgen05.ld.sync.aligned.32x32b.x32.b32 "                              \
        "{%0, %1, %2, %3, %4, %5, %6, %7, "                                             \
        " %8, %9, %10, %11, %12, %13, %14, %15, "                                       \
        " %16, %17, %18, %19, %20, %21, %22, %23, "                                     \
        " %24, %25, %26, %27, %28, %29, %30, %31}, [%32];"                              \
        : "=r"((r)[0]),  "=r"((r)[1]),  "=r"((r)[2]),  "=r"((r)[3]),                    \
          "=r"((r)[4]),  "=r"((r)[5]),  "=r"((r)[6]),  "=r"((r)[7]),                    \
          "=r"((r)[8]),  "=r"((r)[9]),  "=r"((r)[10]), "=r"((r)[11]),                   \
          "=r"((r)[12]), "=r"((r)[13]), "=r"((r)[14]), "=r"((r)[15]),                   \
          "=r"((r)[16]), "=r"((r)[17]), "=r"((r)[18]), "=r"((r)[19]),                   \
          "=r"((r)[20]), "=r"((r)[21]), "=r"((r)[22]), "=r"((r)[23]),                   \
          "=r"((r)[24]), "=r"((r)[25]), "=r"((r)[26]), "=r"((r)[27]),                   \
          "=r"((r)[28]), "=r"((r)[29]), "=r"((r)[30]), "=r"((r)[31])                    \
        : "r"(tmem_addr))

__device__ __forceinline__ void mma_f16_ss(uint32_t d_tmem, uint64_t a_desc,
                                           uint64_t b_desc, uint32_t idesc, bool acc) {
    uint32_t en = acc ? 1u : 0u;
    uint32_t z = 0;
    asm volatile(
        "{\n\t.reg .pred p;\n\tsetp.ne.u32 p, %5, 0;\n\t"
        "tcgen05.mma.cta_group::1.kind::f16 [%0], %1, %2, %3, {%4, %4, %4, %4}, p;\n\t}"
        :: "r"(d_tmem), "l"(a_desc), "l"(b_desc), "r"(idesc), "r"(z), "r"(en)
        : "memory");
}

__device__ __forceinline__ uint64_t make_desc(uint32_t addr) {
    return ((uint64_t)2 << 61) | ((uint64_t)1 << 46) | ((uint64_t)64 << 32)
         | ((uint64_t)1 << 16) | (uint64_t)((addr >> 4) & 0x3FFF);
}

__device__ __forceinline__ uint32_t swz(uint32_t off) {
    return off ^ ((off >> 3) & 0x70);
}
#endif // HAVE_TCGEN05

// Fused dequant + tcgen05 GEMM. Empty stub unless sm_103a features compiled.
__global__ void __launch_bounds__(NTHREADS, 1)
gemm_tc_kernel(const int* __restrict__ packed) {
#ifdef HAVE_TCGEN05
    extern __shared__ char smem[];
    const uint32_t smem_base = smem_u32(smem);
    const int tid = threadIdx.x;
    const int wid = tid >> 5;
    const int lid = tid & 31;
    const int tile = blockIdx.x;      // 0..31
    const int ks   = blockIdx.y;      // 0..3
    const long row0 = (long)tile * TC_TILE_M;
    const int  k0   = ks * TC_KS_LEN;

    if (wid == 0) {
        TCGEN05_ALLOC(smem_base + SMEM_TMEM_PTR, 512);
        TCGEN05_RELINQUISH();
    }
    if (tid == 0) {
        MBARRIER_INIT(smem_base + SMEM_MBAR + 0, 1);
        MBARRIER_INIT(smem_base + SMEM_MBAR + 8, 1);
    }
    __syncthreads();
    uint32_t tmem_base;
    asm volatile("ld.shared.b32 %0, [%1];" : "=r"(tmem_base) : "r"(smem_base + SMEM_TMEM_PTR));

    for (int c = 0; c < TC_NCHUNKS; ++c) {
        const int buf = c & 1;
        const uint32_t mbar = smem_base + SMEM_MBAR + buf * 8;
        if (c >= 2) MBARRIER_WAIT_PARITY(mbar, ((c >> 1) - 1) & 1);
        const int abase = SMEM_BUF0 + buf * BUF_STRIDE;
        const int kc = k0 + c * TC_KCHUNK;

        #pragma unroll
        for (int j = 0; j < 16; ++j) {
            const int i = tid + j * NTHREADS;
            const int r  = i >> 5;
            const int c4 = (i & 31) << 2;
            const int4 v = *(const int4*)(packed + (row0 + r) * (long)IC + kc + c4);
            __nv_bfloat162 pl0 = __floats2bfloat162_rn((float)(v.x & 15), (float)(v.y & 15));
            __nv_bfloat162 pl1 = __floats2bfloat162_rn((float)(v.z & 15), (float)(v.w & 15));
            __nv_bfloat162 ph0 = __floats2bfloat162_rn((float)((v.x >> 4) & 15), (float)((v.y >> 4) & 15));
            __nv_bfloat162 ph1 = __floats2bfloat162_rn((float)((v.z >> 4) & 15), (float)((v.w >> 4) & 15));
            uint32_t off = ((uint32_t)(c4 >> 6) << 14) + (uint32_t)r * 128 + ((uint32_t)(c4 & 63) << 1);
            off = swz(off);
            uint2 ul, uh;
            ul.x = *(uint32_t*)&pl0; ul.y = *(uint32_t*)&pl1;
            uh.x = *(uint32_t*)&ph0; uh.y = *(uint32_t*)&ph1;
            *(uint2*)(smem + abase + off)              = ul;
            *(uint2*)(smem + abase + A_HIGH_OFF + off) = uh;
        }

        #pragma unroll
        for (int j = 0; j < 8; ++j) {
            const int i = tid + j * NTHREADS;
            const int r = i >> 4;
            const int cc = (i & 15) << 3;
            const float4 v = *(const float4*)(g_xhl + (long)r * IC + kc + cc);
            uint32_t off = ((uint32_t)(cc >> 6) << 14) + (uint32_t)r * 128 + ((uint32_t)(cc & 63) << 1);
            off = swz(off);
            *(float4*)(smem + abase + B_OFF + off) = v;
        }

        asm volatile("fence.proxy.async.shared::cta;" ::: "memory");
        __syncthreads();

        if (wid == 0) {
            TCGEN05_FENCE_AFTER();
            const uint64_t adl = make_desc(smem_base + abase);
            const uint64_t adh = make_desc(smem_base + abase + A_HIGH_OFF);
            const uint64_t bd  = make_desc(smem_base + abase + B_OFF);
            if (elect_one()) {
                #pragma unroll
                for (int m = 0; m < 8; ++m) {
                    const uint64_t doff = (uint64_t)((m >> 2) * 1024 + (m & 3) * 2);
                    const bool acc = !(c == 0 && m == 0);
                    mma_f16_ss(tmem_base,       adl + doff, bd + doff, MMA_IDESC, acc);
                    mma_f16_ss(tmem_base + 128, adh + doff, bd + doff, MMA_IDESC, acc);
                }
                TCGEN05_COMMIT(mbar);
            }
        }
    }

    MBARRIER_WAIT_PARITY(smem_base + SMEM_MBAR + 8, (TC_NCHUNKS / 2 - 1) & 1);
    TCGEN05_FENCE_AFTER();

    {
        const int part = wid >> 2;
        const uint32_t td = tmem_base + part * 128;
        const long ocg = (part ? (long)PROWS : 0L) + row0 + (wid & 3) * 32 + lid;
        #pragma unroll
        for (int half = 0; half < 2; ++half) {
            uint32_t da[32], db[32];
            TCGEN05_LD_X32(da, td + half * 32);
            TCGEN05_LD_X32(db, td + 64 + half * 32);
            TCGEN05_WAIT_LD();
            #pragma unroll
            for (int j = 0; j < 32; ++j) {
                const int b = half * 32 + j;
                const float v = __uint_as_float(da[j]) + __uint_as_float(db[j]);
                g_partial[(long)(ks * BATCH + b) * OC + ocg] = v;          // slot ks
                g_partial[(long)((4 + ks) * BATCH + b) * OC + ocg] = 0.f;  // zero lo slot
            }
        }
    }
    TCGEN05_FENCE_BEFORE();
    __syncthreads();
    if (wid == 0) TCGEN05_DEALLOC(tmem_base, 512);
#endif
}

// ---------------------------------------------------------------------------
// Fallback: mma.sync.m16n8k16 bf16 GEMM (compiles on plain sm_103)
//   grid (64, 4): blockIdx.x = 64 packed rows -> 128 oc (64 low + 64 high)
//   N = 128 x-rows (64 hi comp + 64 lo comp); k-extent 2048 per CTA.
//   hi-comp results -> slot ks, lo-comp -> slot 4+ks.
// ---------------------------------------------------------------------------
__global__ void __launch_bounds__(256, 2)
gemm_fb_kernel(const int* __restrict__ packed) {
#if defined(__CUDA_ARCH__) && !defined(__CUDA_ARCH_FEAT_SM103_ALL)
    extern __shared__ char smem[];
    int* sA = (int*)smem;                                       // [2][64][72] int32
    __nv_bfloat16* sB = (__nv_bfloat16*)(smem + FB_SA_BYTES);   // [2][128][72] bf16

    const int tid  = threadIdx.x;
    const int wid  = tid >> 5, lane = tid & 31;
    const int g    = lane >> 2, t = lane & 3;
    const int wr   = wid & 3,  wc = wid >> 2;
    const int p0   = blockIdx.x * FB_TILE_P;
    const int ks   = blockIdx.y;
    const int k0   = ks * FB_KEXT;
    const bool high = (wr >= 2);

    float acc[2][8][4];
    #pragma unroll
    for (int i = 0; i < 2; ++i)
        #pragma unroll
        for (int j = 0; j < 8; ++j)
            #pragma unroll
            for (int q = 0; q < 4; ++q) acc[i][j][q] = 0.f;

    auto issue = [&](int c) {
        const int buf = c & 1;
        const int kc = k0 + c * FB_KC;
        const uint32_t sa = smem_u32(sA + buf * FB_TILE_P * SA_STRIDE);
        const uint32_t sb = smem_u32(sB + buf * 128 * SB_STRIDE);
        #pragma unroll
        for (int j = 0; j < 4; ++j) {
            const int i = tid + j * 256;
            const int r = i >> 4, s = i & 15;
            cp16(sa + (uint32_t)(r * SA_STRIDE + s * 4) * 4,
                 packed + (long)(p0 + r) * IC + kc + s * 4);
        }
        #pragma unroll
        for (int j = 0; j < 4; ++j) {
            const int i = tid + j * 256;
            const int r = i >> 3, s = i & 7;
            cp16(sb + (uint32_t)(r * SB_STRIDE + s * 8) * 2,
                 g_xhl + (long)r * IC + kc + s * 8);
        }
        CP_COMMIT();
    };

    issue(0);
    for (int c = 0; c < FB_NCH; ++c) {
        if (c + 1 < FB_NCH) issue(c + 1);
        else CP_COMMIT();       // empty group keeps the wait count uniform
        CP_WAIT1();
        __syncthreads();

        const int buf = c & 1;
        const int* A = sA + buf * FB_TILE_P * SA_STRIDE;
        const __nv_bfloat16* B = sB + buf * 128 * SB_STRIDE;

        #pragma unroll
        for (int kk = 0; kk < 4; ++kk) {
            uint32_t af[2][4];
            #pragma unroll
            for (int mi = 0; mi < 2; ++mi) {
                const int prb = (wr & 1) * 32 + mi * 16 + g;
                #pragma unroll
                for (int kh = 0; kh < 2; ++kh) {
                    #pragma unroll
                    for (int hr = 0; hr < 2; ++hr) {
                        const int2 v = *(const int2*)(A + (prb + hr * 8) * SA_STRIDE
                                                        + kk * 16 + 2 * t + kh * 8);
                        int q0, q1;
                        if (high) { q0 = (v.x >> 4) & 15; q1 = (v.y >> 4) & 15; }
                        else      { q0 = v.x & 15;        q1 = v.y & 15; }
                        __nv_bfloat162 p = __floats2bfloat162_rn((float)q0, (float)q1);
                        af[mi][hr + 2 * kh] = *(uint32_t*)&p;
                    }
                }
            }
            #pragma unroll
            for (int nf = 0; nf < 8; ++nf) {
                const int n = wc * 64 + nf * 8 + g;
                uint32_t bf[2];
                bf[0] = *(const uint32_t*)(B + n * SB_STRIDE + kk * 16 + 2 * t);
                bf[1] = *(const uint32_t*)(B + n * SB_STRIDE + kk * 16 + 2 * t + 8);
                mma16816(acc[0][nf], af[0], bf);
                mma16816(acc[1][nf], af[1], bf);
            }
        }
        __syncthreads();
    }

    // epilogue: scatter partials
    #pragma unroll
    for (int mi = 0; mi < 2; ++mi)
        #pragma unroll
        for (int nf = 0; nf < 8; ++nf)
            #pragma unroll
            for (int q = 0; q < 4; ++q) {
                const int m = wr * 32 + mi * 16 + g + (q >> 1) * 8;
                const int n = wc * 64 + nf * 8 + 2 * t + (q & 1);
                const long oc = (high ? (long)PROWS : 0L) + p0 + (m & 63);
                const int slot = (n < 64) ? ks : (4 + ks);
                const int b = n & 63;
                g_partial[((long)slot * BATCH + b) * OC + oc] = acc[mi][nf][q];
            }
#endif
}

// ---------------------------------------------------------------------------
// Reduce: sum 8 slots + affine epilogue
// ---------------------------------------------------------------------------
__global__ void reduce_kernel(const float* __restrict__ delta,
                              const float* __restrict__ zp,
                              const float* __restrict__ bias,
                              float* __restrict__ out) {
    const int idx = blockIdx.x * blockDim.x + threadIdx.x;  // b*8192 + oc
    const int b  = idx >> 13;
    const int oc = idx & (OC - 1);
    float dot = 0.f;
    #pragma unroll
    for (int s = 0; s < 8; ++s)
        dot += g_partial[(long)(s * BATCH + b) * OC + oc];
    out[idx] = delta[oc] * (dot - zp[oc] * g_S[b]) + bias[oc];
}

// ---------------------------------------------------------------------------
// Launch (runtime dispatch: the stubbed-out kernel compiles to ~0 registers)
// ---------------------------------------------------------------------------
extern "C" void kernel_launch(void* const* d_in, const int* in_sizes, int n_in,
                              void* d_out, int out_size) {
    const float* x      = (const float*)d_in[0];
    const int*   packed = (const int*)d_in[1];
    const float* delta  = (const float*)d_in[2];
    const float* zp     = (const float*)d_in[3];
    const float* bias   = (const float*)d_in[4];
    float* out = (float*)d_out;

    cudaFuncSetAttribute(gemm_tc_kernel, cudaFuncAttributeMaxDynamicSharedMemorySize, TC_SMEM_TOTAL);
    cudaFuncSetAttribute(gemm_fb_kernel, cudaFuncAttributeMaxDynamicSharedMemorySize, FB_SMEM_TOTAL);

    cudaFuncAttributes fa{};
    cudaFuncGetAttributes(&fa, (const void*)gemm_tc_kernel);
    const bool use_tc = fa.numRegs > 40;   // stub body -> tiny reg count

    prep_kernel<<<BATCH, 256>>>(x);
    if (use_tc)
        gemm_tc_kernel<<<dim3(32, KSPLIT), NTHREADS, TC_SMEM_TOTAL>>>(packed);
    else
        gemm_fb_kernel<<<dim3(64, KSPLIT), 256, FB_SMEM_TOTAL>>>(packed);
    reduce_kernel<<<(BATCH * OC) / 256, 256>>>(delta, zp, bias, out);
}